// round 1
// baseline (speedup 1.0000x reference)
#include <cuda_runtime.h>
#include <math.h>

#define MAXN 50000
#define MAXC 128

// ---------------- device scratch (no allocations allowed) ----------------
__device__ float g_X  [MAXN * MAXC];
__device__ float g_Y  [MAXN * MAXC];
__device__ float g_M  [MAXN * MAXC];
__device__ float g_AGG[MAXN * MAXC];
__device__ float g_GI [MAXN * 3 * MAXC];
__device__ float g_GH [MAXN * 3 * MAXC];
__device__ float g_POOL[256 * 128];
__device__ float g_FC1 [256 * 256];
__device__ int   g_flags[2];   // [0]=edge_index is int64, [1]=batch is int64

// ---------------- dtype detection (int64 vs int32 indices) ----------------
// edge values are random in [0,50000): hi-words of first 64 int64 elems are 0;
// as int32 the same words are random values (P[all zero] ~ 0).
// batch is sorted in [0,256): check hi-words of elements near N/2; as int32
// those words hold batch[~N-1] ~ 255 (nonzero); as int64 they are 0.
__global__ void detect_kernel(const unsigned* __restrict__ ei,
                              const unsigned* __restrict__ bat, int E, int N) {
    if (blockIdx.x == 0 && threadIdx.x == 0) {
        int e64 = 1;
        for (int i = 0; i < 64; i++)
            if (ei[2 * i + 1] != 0u) { e64 = 0; break; }
        int b64 = 1;
        int b0 = N / 2 - 64;
        for (int i = 0; i < 64; i++)
            if (bat[2 * (b0 + i) + 1] != 0u) { b64 = 0; break; }
        g_flags[0] = e64;
        g_flags[1] = b64;
    }
}

// ---------------- tiled SGEMM: C[n,j] = sum_k A[n,k]*B(k,j) (+bias) ----------------
// TB=false: B row-major [K,J] -> B[k*J+j]   (used for m = x @ W[i])
// TB=true : B row-major [J,K] -> B[j*K+k]   (used for gi/gh/fc1, i.e. @ W^T)
// act: 0=none, 1=ELU
template <bool TB>
__global__ void __launch_bounds__(256) gemm_kernel(
    const float* __restrict__ A, const float* __restrict__ B,
    const float* __restrict__ bias, float* __restrict__ Cmat,
    int N, int K, int J, int act) {
    __shared__ float As[16][64];
    __shared__ float Bs[16][64];
    const int tid = threadIdx.x;
    const int tx = tid & 15, ty = tid >> 4;
    const int row0 = blockIdx.y * 64;
    const int col0 = blockIdx.x * 64;

    float acc[4][4];
#pragma unroll
    for (int i = 0; i < 4; i++)
#pragma unroll
        for (int j = 0; j < 4; j++) acc[i][j] = 0.f;

    for (int kt = 0; kt < K; kt += 16) {
#pragma unroll
        for (int l = tid; l < 1024; l += 256) {   // A tile 64x16
            int k = l & 15, m = l >> 4;
            int r = row0 + m;
            As[k][m] = (r < N) ? A[(size_t)r * K + kt + k] : 0.f;
        }
        if (TB) {
#pragma unroll
            for (int l = tid; l < 1024; l += 256) {  // B^T tile
                int k = l & 15, j = l >> 4;
                int c = col0 + j;
                Bs[k][j] = (c < J) ? B[(size_t)c * K + kt + k] : 0.f;
            }
        } else {
#pragma unroll
            for (int l = tid; l < 1024; l += 256) {  // B tile
                int j = l & 63, k = l >> 6;
                int c = col0 + j;
                Bs[k][j] = (c < J) ? B[(size_t)(kt + k) * J + c] : 0.f;
            }
        }
        __syncthreads();
#pragma unroll
        for (int k = 0; k < 16; k++) {
            float4 a4 = *(const float4*)&As[k][ty * 4];
            float4 b4 = *(const float4*)&Bs[k][tx * 4];
            float av[4] = {a4.x, a4.y, a4.z, a4.w};
            float bv[4] = {b4.x, b4.y, b4.z, b4.w};
#pragma unroll
            for (int i = 0; i < 4; i++)
#pragma unroll
                for (int j = 0; j < 4; j++) acc[i][j] += av[i] * bv[j];
        }
        __syncthreads();
    }

#pragma unroll
    for (int i = 0; i < 4; i++) {
        int r = row0 + ty * 4 + i;
        if (r >= N) continue;
#pragma unroll
        for (int j = 0; j < 4; j++) {
            int c = col0 + tx * 4 + j;
            if (c >= J) continue;
            float v = acc[i][j];
            if (bias) v += bias[c];
            if (act == 1) v = (v > 0.f) ? v : expm1f(v);
            Cmat[(size_t)r * J + c] = v;
        }
    }
}

// ---------------- edge scatter-add: agg[dst] += m[src] ----------------
__global__ void scatter_kernel(const float* __restrict__ m, float* __restrict__ agg,
                               const void* __restrict__ ei, int E, int C) {
    int cq = C >> 2;
    long long idx = (long long)blockIdx.x * blockDim.x + threadIdx.x;
    long long total = (long long)E * cq;
    if (idx >= total) return;
    int e = (int)(idx / cq);
    int c4 = (int)(idx - (long long)e * cq) << 2;
    int src, dst;
    if (g_flags[0]) {
        const long long* p = (const long long*)ei;
        src = (int)p[e]; dst = (int)p[E + e];
    } else {
        const int* p = (const int*)ei;
        src = p[e]; dst = p[E + e];
    }
    float4 v = *(const float4*)(m + (size_t)src * C + c4);
    float* o = agg + (size_t)dst * C + c4;
    atomicAdd(o + 0, v.x);
    atomicAdd(o + 1, v.y);
    atomicAdd(o + 2, v.z);
    atomicAdd(o + 3, v.w);
}

// ---------------- GRU pointwise update ----------------
__global__ void gru_kernel(float* __restrict__ x, const float* __restrict__ gi,
                           const float* __restrict__ gh, int N, int C) {
    long long idx = (long long)blockIdx.x * blockDim.x + threadIdx.x;
    if (idx >= (long long)N * C) return;
    int n = (int)(idx / C);
    int j = (int)(idx - (long long)n * C);
    const float* gin = gi + (size_t)n * 3 * C;
    const float* ghn = gh + (size_t)n * 3 * C;
    float ir = gin[j], iz = gin[C + j], in_ = gin[2 * C + j];
    float hr = ghn[j], hz = ghn[C + j], hn = ghn[2 * C + j];
    float r = 1.f / (1.f + expf(-(ir + hr)));
    float z = 1.f / (1.f + expf(-(iz + hz)));
    float nn = tanhf(in_ + r * hn);
    float xo = x[(size_t)n * C + j];
    x[(size_t)n * C + j] = (1.f - z) * nn + z * xo;
}

// ---------------- ELU (+optional BN eval) + zero-pad to wider C ----------------
__global__ void transition_kernel(const float* __restrict__ in, float* __restrict__ out,
                                  int N, int Cin, int Cout,
                                  const float* __restrict__ gamma,
                                  const float* __restrict__ beta,
                                  const float* __restrict__ mean,
                                  const float* __restrict__ var) {
    long long idx = (long long)blockIdx.x * blockDim.x + threadIdx.x;
    if (idx >= (long long)N * Cout) return;
    int n = (int)(idx / Cout);
    int j = (int)(idx - (long long)n * Cout);
    float v = 0.f;
    if (j < Cin) {
        v = in[(size_t)n * Cin + j];
        v = (v > 0.f) ? v : expm1f(v);  // ELU
        if (gamma) v = (v - mean[j]) * rsqrtf(var[j] + 1e-5f) * gamma[j] + beta[j];
    }
    out[(size_t)n * Cout + j] = v;
}

// ---------------- global add pool ----------------
__global__ void pool_kernel(const float* __restrict__ h, const void* __restrict__ batch,
                            float* __restrict__ pool, int N) {
    long long idx = (long long)blockIdx.x * blockDim.x + threadIdx.x;
    if (idx >= (long long)N * 128) return;
    int n = (int)(idx >> 7);
    int c = (int)(idx & 127);
    int g = g_flags[1] ? (int)((const long long*)batch)[n] : ((const int*)batch)[n];
    atomicAdd(&pool[g * 128 + c], h[idx]);
}

// ---------------- fc2 + log_softmax (per graph row) ----------------
__global__ void fc2_kernel(const float* __restrict__ g, const float* __restrict__ W,
                           const float* __restrict__ b, float* __restrict__ out) {
    int row = blockIdx.x;
    int lane = threadIdx.x;  // 32 threads
    __shared__ float logits[10];
    for (int j = 0; j < 10; j++) {
        float s = 0.f;
        for (int k = lane; k < 256; k += 32) s += g[row * 256 + k] * W[j * 256 + k];
#pragma unroll
        for (int o = 16; o > 0; o >>= 1) s += __shfl_down_sync(0xffffffffu, s, o);
        if (lane == 0) logits[j] = s + b[j];
    }
    __syncthreads();
    if (lane == 0) {
        float mx = logits[0];
        for (int j = 1; j < 10; j++) mx = fmaxf(mx, logits[j]);
        float se = 0.f;
        for (int j = 0; j < 10; j++) se += expf(logits[j] - mx);
        float lse = mx + logf(se);
        for (int j = 0; j < 10; j++) out[row * 10 + j] = logits[j] - lse;
    }
}

static inline int ceildiv(int a, int b) { return (a + b - 1) / b; }

extern "C" void kernel_launch(void* const* d_in, const int* in_sizes, int n_in,
                              void* d_out, int out_size) {
    // metadata order (setup_inputs dict order):
    const float* x_in  = (const float*)d_in[0];
    const void*  ei    = d_in[1];
    const void*  batch = d_in[2];
    const float* fc1W  = (const float*)d_in[3];
    const float* fc1b  = (const float*)d_in[4];
    const float* fc2W  = (const float*)d_in[5];
    const float* fc2b  = (const float*)d_in[6];
    const float* cW[3]   = {(const float*)d_in[7],  (const float*)d_in[12], (const float*)d_in[17]};
    const float* cwih[3] = {(const float*)d_in[8],  (const float*)d_in[13], (const float*)d_in[18]};
    const float* cwhh[3] = {(const float*)d_in[9],  (const float*)d_in[14], (const float*)d_in[19]};
    const float* cbih[3] = {(const float*)d_in[10], (const float*)d_in[15], (const float*)d_in[20]};
    const float* cbhh[3] = {(const float*)d_in[11], (const float*)d_in[16], (const float*)d_in[21]};
    const float* bng[2]  = {(const float*)d_in[22], (const float*)d_in[26]};
    const float* bnb[2]  = {(const float*)d_in[23], (const float*)d_in[27]};
    const float* bnm[2]  = {(const float*)d_in[24], (const float*)d_in[28]};
    const float* bnv[2]  = {(const float*)d_in[25], (const float*)d_in[29]};

    const int N = in_sizes[2];       // 50000
    const int E = in_sizes[1] / 2;   // 800000
    const int Cs[3] = {32, 64, 128};

    float *X, *Y, *M, *AGG, *GI, *GH, *POOL, *FC1;
    cudaGetSymbolAddress((void**)&X, g_X);
    cudaGetSymbolAddress((void**)&Y, g_Y);
    cudaGetSymbolAddress((void**)&M, g_M);
    cudaGetSymbolAddress((void**)&AGG, g_AGG);
    cudaGetSymbolAddress((void**)&GI, g_GI);
    cudaGetSymbolAddress((void**)&GH, g_GH);
    cudaGetSymbolAddress((void**)&POOL, g_POOL);
    cudaGetSymbolAddress((void**)&FC1, g_FC1);

    detect_kernel<<<1, 1>>>((const unsigned*)ei, (const unsigned*)batch, E, N);

    // x (N x 32) -> working buffer
    cudaMemcpyAsync(X, x_in, (size_t)N * 32 * sizeof(float), cudaMemcpyDeviceToDevice);

    float* xcur = X;
    float* xnext = Y;
    for (int L = 0; L < 3; L++) {
        const int C = Cs[L];
        const int C3 = 3 * C;
        dim3 gm(ceildiv(C, 64), ceildiv(N, 64));
        dim3 gg(ceildiv(C3, 64), ceildiv(N, 64));
        for (int it = 0; it < 4; it++) {
            // m = x @ W[it]
            gemm_kernel<false><<<gm, 256>>>(xcur, cW[L] + (size_t)it * C * C, nullptr, M, N, C, C, 0);
            // agg = scatter_add(m[src] -> dst)
            cudaMemsetAsync(AGG, 0, (size_t)N * C * sizeof(float));
            long long tot = (long long)E * (C / 4);
            scatter_kernel<<<(int)((tot + 255) / 256), 256>>>(M, AGG, ei, E, C);
            // gi = agg @ wih^T + bih ; gh = x @ whh^T + bhh
            gemm_kernel<true><<<gg, 256>>>(AGG, cwih[L], cbih[L], GI, N, C, C3, 0);
            gemm_kernel<true><<<gg, 256>>>(xcur, cwhh[L], cbhh[L], GH, N, C, C3, 0);
            // x = GRU(agg-part, x-part)
            long long tn = (long long)N * C;
            gru_kernel<<<(int)((tn + 255) / 256), 256>>>(xcur, GI, GH, N, C);
        }
        // ELU (+BN for layers 0,1), pad to next width
        const int Cout = (L < 2) ? Cs[L + 1] : Cs[L];
        const float* ga = (L < 2) ? bng[L] : nullptr;
        const float* be = (L < 2) ? bnb[L] : nullptr;
        const float* mn = (L < 2) ? bnm[L] : nullptr;
        const float* vr = (L < 2) ? bnv[L] : nullptr;
        long long tt = (long long)N * Cout;
        transition_kernel<<<(int)((tt + 255) / 256), 256>>>(xcur, xnext, N, C, Cout, ga, be, mn, vr);
        float* t = xcur; xcur = xnext; xnext = t;
    }

    // global add pool -> [256,128]
    cudaMemsetAsync(POOL, 0, 256 * 128 * sizeof(float));
    pool_kernel<<<ceildiv(N * 128, 256), 256>>>(xcur, batch, POOL, N);

    // fc1 + ELU: [256,128] @ [256,128]^T -> [256,256]
    gemm_kernel<true><<<dim3(4, 4), 256>>>(POOL, fc1W, fc1b, FC1, 256, 128, 256, 1);

    // fc2 + log_softmax -> [256,10]
    fc2_kernel<<<256, 32>>>(FC1, fc2W, fc2b, (float*)d_out);
}

// round 2
// speedup vs baseline: 1.5603x; 1.5603x over previous
#include <cuda_runtime.h>
#include <math.h>

#define MAXN 50000
#define MAXE 800000

// ---------------- device scratch (no allocations allowed) ----------------
__device__ float g_X  [MAXN * 128];
__device__ float g_Y  [MAXN * 128];
__device__ float g_MGH[MAXN * 512];      // [m | gh] concat, row stride 4C
__device__ float g_GI [MAXN * 384];
__device__ float g_AGG[MAXN * 128];
__device__ float g_POOL[256 * 128];
__device__ float g_FC1 [256 * 256];
__device__ int   g_src[MAXE];
__device__ int   g_dst[MAXE];
__device__ int   g_b32[MAXN];
__device__ float g_BC [344064];          // concat weights [C x 4C] x 4 iters x 3 layers
__device__ float g_BIH[64512];           // wih^T per layer
__device__ float g_BCB[896];             // concat bias per layer (0.. | bhh)
__device__ float g_FC1T[128 * 256];      // fc1_W^T
__device__ int   g_flags[2];             // [0]=edge_index is int64, [1]=batch is int64

// ---------------- dtype detection (int64 vs int32 indices) ----------------
__global__ void detect_kernel(const unsigned* __restrict__ ei,
                              const unsigned* __restrict__ bat, int E, int N) {
    if (blockIdx.x == 0 && threadIdx.x == 0) {
        int e64 = 1;
        for (int i = 0; i < 64; i++)
            if (ei[2 * i + 1] != 0u) { e64 = 0; break; }
        int b64 = 1;
        int b0 = N / 2 - 64;
        for (int i = 0; i < 64; i++)
            if (bat[2 * (b0 + i) + 1] != 0u) { b64 = 0; break; }
        g_flags[0] = e64;
        g_flags[1] = b64;
    }
}

// ---------------- index conversion to int32 ----------------
__global__ void convert_idx(const void* __restrict__ ei, const void* __restrict__ bat,
                            int E, int N) {
    int i = blockIdx.x * blockDim.x + threadIdx.x;
    if (i < E) {
        if (g_flags[0]) {
            const long long* p = (const long long*)ei;
            g_src[i] = (int)p[i];
            g_dst[i] = (int)p[E + i];
        } else {
            const int* p = (const int*)ei;
            g_src[i] = p[i];
            g_dst[i] = p[E + i];
        }
    }
    if (i < N)
        g_b32[i] = g_flags[1] ? (int)((const long long*)bat)[i] : ((const int*)bat)[i];
}

// ---------------- weight prep: Bcat = [W(it) | whh^T], BihT = wih^T, bias_cat ----------------
__global__ void prep_weights(const float* __restrict__ W, const float* __restrict__ whh,
                             const float* __restrict__ wih, const float* __restrict__ bhh,
                             float* __restrict__ Bcat, float* __restrict__ BihT,
                             float* __restrict__ bcat, int C) {
    const int C3 = 3 * C, C4 = 4 * C;
    long long stride = (long long)gridDim.x * blockDim.x;
    long long t0 = (long long)blockIdx.x * blockDim.x + threadIdx.x;
    long long tot1 = 4LL * C * C4;
    for (long long idx = t0; idx < tot1; idx += stride) {
        int it = (int)(idx / (C * C4));
        int rem = (int)(idx % (C * C4));
        int k = rem / C4, j = rem % C4;
        Bcat[idx] = (j < C) ? W[(size_t)it * C * C + k * C + j]
                            : whh[(size_t)(j - C) * C + k];
    }
    long long tot2 = (long long)C * C3;
    for (long long idx = t0; idx < tot2; idx += stride) {
        int k = (int)(idx / C3), j = (int)(idx % C3);
        BihT[idx] = wih[(size_t)j * C + k];
    }
    for (long long idx = t0; idx < C4; idx += stride)
        bcat[idx] = (idx < C) ? 0.f : bhh[idx - C];
}

__global__ void transpose_fc1(const float* __restrict__ Wi, float* __restrict__ Wt) {
    int idx = blockIdx.x * blockDim.x + threadIdx.x;  // 128*256
    if (idx >= 128 * 256) return;
    int k = idx / 256, j = idx % 256;
    Wt[idx] = Wi[(size_t)j * 128 + k];
}

// ---------------- 128x128 tiled SGEMM, 8x8 micro, double-buffered ----------------
// C[n,j] = sum_k A[n,k] * B[k,j] (+bias[j]) ; act: 0=none, 1=ELU
// Requires K % 16 == 0, J % 4 == 0.
__global__ void __launch_bounds__(256, 2) gemm128(
    const float* __restrict__ A, const float* __restrict__ B,
    const float* __restrict__ bias, float* __restrict__ Cmat,
    int N, int K, int J, int act) {
    __shared__ float As[2][16][128];
    __shared__ float Bs[2][16][128];
    const int tid = threadIdx.x;
    const int tx = tid & 15, ty = tid >> 4;
    const int row0 = blockIdx.y * 128, col0 = blockIdx.x * 128;
    const int ar = tid >> 2, af = (tid & 3) << 2;       // A loader: row, k-float4
    const int bk = tid >> 5, bc = (tid & 31) << 2;      // B loader: k-row, col-float4

    float acc[8][8];
#pragma unroll
    for (int i = 0; i < 8; i++)
#pragma unroll
        for (int j = 0; j < 8; j++) acc[i][j] = 0.f;

    const int nk = K >> 4;

    // prologue: load tile 0 into buffer 0
    {
#pragma unroll
        for (int h = 0; h < 2; h++) {
            int r = row0 + ar + h * 64;
            float4 v = make_float4(0.f, 0.f, 0.f, 0.f);
            if (r < N) v = *(const float4*)(A + (size_t)r * K + af);
            As[0][af + 0][ar + h * 64] = v.x;
            As[0][af + 1][ar + h * 64] = v.y;
            As[0][af + 2][ar + h * 64] = v.z;
            As[0][af + 3][ar + h * 64] = v.w;
        }
#pragma unroll
        for (int h = 0; h < 2; h++) {
            int k = bk + h * 8;
            int c = col0 + bc;
            float4 v = make_float4(0.f, 0.f, 0.f, 0.f);
            if (c < J) v = *(const float4*)(B + (size_t)k * J + c);
            *(float4*)&Bs[0][k][bc] = v;
        }
    }
    __syncthreads();

    for (int t = 0; t < nk; t++) {
        int s = t & 1;
        if (t + 1 < nk) {
            int kt = (t + 1) << 4;
#pragma unroll
            for (int h = 0; h < 2; h++) {
                int r = row0 + ar + h * 64;
                float4 v = make_float4(0.f, 0.f, 0.f, 0.f);
                if (r < N) v = *(const float4*)(A + (size_t)r * K + kt + af);
                As[s ^ 1][af + 0][ar + h * 64] = v.x;
                As[s ^ 1][af + 1][ar + h * 64] = v.y;
                As[s ^ 1][af + 2][ar + h * 64] = v.z;
                As[s ^ 1][af + 3][ar + h * 64] = v.w;
            }
#pragma unroll
            for (int h = 0; h < 2; h++) {
                int k = bk + h * 8;
                int c = col0 + bc;
                float4 v = make_float4(0.f, 0.f, 0.f, 0.f);
                if (c < J) v = *(const float4*)(B + (size_t)(kt + k) * J + c);
                *(float4*)&Bs[s ^ 1][k][bc] = v;
            }
        }
#pragma unroll
        for (int k = 0; k < 16; k++) {
            float a[8], b[8];
            *(float4*)&a[0] = *(const float4*)&As[s][k][ty * 4];
            *(float4*)&a[4] = *(const float4*)&As[s][k][64 + ty * 4];
            *(float4*)&b[0] = *(const float4*)&Bs[s][k][tx * 4];
            *(float4*)&b[4] = *(const float4*)&Bs[s][k][64 + tx * 4];
#pragma unroll
            for (int i = 0; i < 8; i++)
#pragma unroll
                for (int j = 0; j < 8; j++) acc[i][j] += a[i] * b[j];
        }
        __syncthreads();
    }

    // epilogue
#pragma unroll
    for (int gi = 0; gi < 2; gi++)
#pragma unroll
        for (int i = 0; i < 4; i++) {
            int r = row0 + gi * 64 + ty * 4 + i;
            if (r >= N) continue;
#pragma unroll
            for (int gj = 0; gj < 2; gj++) {
                int c = col0 + gj * 64 + tx * 4;
                if (c >= J) continue;
                float4 v;
                v.x = acc[gi * 4 + i][gj * 4 + 0];
                v.y = acc[gi * 4 + i][gj * 4 + 1];
                v.z = acc[gi * 4 + i][gj * 4 + 2];
                v.w = acc[gi * 4 + i][gj * 4 + 3];
                if (bias) {
                    float4 bv = *(const float4*)(bias + c);
                    v.x += bv.x; v.y += bv.y; v.z += bv.z; v.w += bv.w;
                }
                if (act == 1) {
                    v.x = (v.x > 0.f) ? v.x : expm1f(v.x);
                    v.y = (v.y > 0.f) ? v.y : expm1f(v.y);
                    v.z = (v.z > 0.f) ? v.z : expm1f(v.z);
                    v.w = (v.w > 0.f) ? v.w : expm1f(v.w);
                }
                *(float4*)(Cmat + (size_t)r * J + c) = v;
            }
        }
}

// ---------------- edge scatter-add: agg[dst] += m[src] (m row stride = mstride) ----------------
__global__ void scatter_kernel(const float* __restrict__ m, int mstride,
                               float* __restrict__ agg, int E, int C) {
    int cq = C >> 2;
    long long idx = (long long)blockIdx.x * blockDim.x + threadIdx.x;
    long long total = (long long)E * cq;
    if (idx >= total) return;
    int e = (int)(idx / cq);
    int c4 = (int)(idx - (long long)e * cq) << 2;
    int src = g_src[e], dst = g_dst[e];
    float4 v = *(const float4*)(m + (size_t)src * mstride + c4);
    float* o = agg + (size_t)dst * C + c4;
    atomicAdd(o + 0, v.x);
    atomicAdd(o + 1, v.y);
    atomicAdd(o + 2, v.z);
    atomicAdd(o + 3, v.w);
}

// ---------------- GRU pointwise: x = (1-z)*n + z*x ----------------
__global__ void gru_kernel(float* __restrict__ x, const float* __restrict__ gi,
                           const float* __restrict__ mgh, int N, int C) {
    const int cq = C >> 2, C3 = 3 * C, C4 = 4 * C;
    long long idx = (long long)blockIdx.x * blockDim.x + threadIdx.x;
    if (idx >= (long long)N * cq) return;
    int n = (int)(idx / cq);
    int j = (int)(idx - (long long)n * cq) << 2;
    const float* gin = gi + (size_t)n * C3 + j;
    const float* ghn = mgh + (size_t)n * C4 + C + j;
    float* xp = x + (size_t)n * C + j;
    float4 ir = *(const float4*)(gin);
    float4 iz = *(const float4*)(gin + C);
    float4 in_ = *(const float4*)(gin + 2 * C);
    float4 hr = *(const float4*)(ghn);
    float4 hz = *(const float4*)(ghn + C);
    float4 hn = *(const float4*)(ghn + 2 * C);
    float4 xo = *(float4*)xp;
    float4 out;
#define GRU1(f)                                                        \
    {                                                                  \
        float r = 1.f / (1.f + expf(-(ir.f + hr.f)));                  \
        float z = 1.f / (1.f + expf(-(iz.f + hz.f)));                  \
        float nn = tanhf(in_.f + r * hn.f);                            \
        out.f = (1.f - z) * nn + z * xo.f;                             \
    }
    GRU1(x) GRU1(y) GRU1(z) GRU1(w)
#undef GRU1
    *(float4*)xp = out;
}

// ---------------- ELU (+optional BN eval) + zero-pad to wider C ----------------
__global__ void transition_kernel(const float* __restrict__ in, float* __restrict__ out,
                                  int N, int Cin, int Cout,
                                  const float* __restrict__ gamma,
                                  const float* __restrict__ beta,
                                  const float* __restrict__ mean,
                                  const float* __restrict__ var) {
    long long idx = (long long)blockIdx.x * blockDim.x + threadIdx.x;
    if (idx >= (long long)N * Cout) return;
    int n = (int)(idx / Cout);
    int j = (int)(idx - (long long)n * Cout);
    float v = 0.f;
    if (j < Cin) {
        v = in[(size_t)n * Cin + j];
        v = (v > 0.f) ? v : expm1f(v);
        if (gamma) v = (v - mean[j]) * rsqrtf(var[j] + 1e-5f) * gamma[j] + beta[j];
    }
    out[(size_t)n * Cout + j] = v;
}

// ---------------- global add pool ----------------
__global__ void pool_kernel(const float* __restrict__ h, float* __restrict__ pool, int N) {
    long long idx = (long long)blockIdx.x * blockDim.x + threadIdx.x;
    if (idx >= (long long)N * 128) return;
    int n = (int)(idx >> 7);
    int c = (int)(idx & 127);
    atomicAdd(&pool[g_b32[n] * 128 + c], h[idx]);
}

// ---------------- fc2 + log_softmax ----------------
__global__ void fc2_kernel(const float* __restrict__ g, const float* __restrict__ W,
                           const float* __restrict__ b, float* __restrict__ out) {
    int row = blockIdx.x;
    int lane = threadIdx.x;
    __shared__ float logits[10];
    for (int j = 0; j < 10; j++) {
        float s = 0.f;
        for (int k = lane; k < 256; k += 32) s += g[row * 256 + k] * W[j * 256 + k];
#pragma unroll
        for (int o = 16; o > 0; o >>= 1) s += __shfl_down_sync(0xffffffffu, s, o);
        if (lane == 0) logits[j] = s + b[j];
    }
    __syncthreads();
    if (lane == 0) {
        float mx = logits[0];
        for (int j = 1; j < 10; j++) mx = fmaxf(mx, logits[j]);
        float se = 0.f;
        for (int j = 0; j < 10; j++) se += expf(logits[j] - mx);
        float lse = mx + logf(se);
        for (int j = 0; j < 10; j++) out[row * 10 + j] = logits[j] - lse;
    }
}

static inline int ceildiv(int a, int b) { return (a + b - 1) / b; }

extern "C" void kernel_launch(void* const* d_in, const int* in_sizes, int n_in,
                              void* d_out, int out_size) {
    const float* x_in  = (const float*)d_in[0];
    const void*  ei    = d_in[1];
    const void*  batch = d_in[2];
    const float* fc1W  = (const float*)d_in[3];
    const float* fc1b  = (const float*)d_in[4];
    const float* fc2W  = (const float*)d_in[5];
    const float* fc2b  = (const float*)d_in[6];
    const float* cW[3]   = {(const float*)d_in[7],  (const float*)d_in[12], (const float*)d_in[17]};
    const float* cwih[3] = {(const float*)d_in[8],  (const float*)d_in[13], (const float*)d_in[18]};
    const float* cwhh[3] = {(const float*)d_in[9],  (const float*)d_in[14], (const float*)d_in[19]};
    const float* cbih[3] = {(const float*)d_in[10], (const float*)d_in[15], (const float*)d_in[20]};
    const float* cbhh[3] = {(const float*)d_in[11], (const float*)d_in[16], (const float*)d_in[21]};
    const float* bng[2]  = {(const float*)d_in[22], (const float*)d_in[26]};
    const float* bnb[2]  = {(const float*)d_in[23], (const float*)d_in[27]};
    const float* bnm[2]  = {(const float*)d_in[24], (const float*)d_in[28]};
    const float* bnv[2]  = {(const float*)d_in[25], (const float*)d_in[29]};

    const int N = in_sizes[2];       // 50000
    const int E = in_sizes[1] / 2;   // 800000
    const int Cs[3] = {32, 64, 128};
    // scratch offsets for prepped weights
    const int bcOff[3]  = {0, 4 * 32 * 128, 4 * 32 * 128 + 4 * 64 * 256};
    const int bihOff[3] = {0, 32 * 96, 32 * 96 + 64 * 192};
    const int bbOff[3]  = {0, 128, 128 + 256};

    float *X, *Y, *MGH, *GI, *AGG, *POOL, *FC1, *BC, *BIH, *BCB, *FC1T;
    cudaGetSymbolAddress((void**)&X, g_X);
    cudaGetSymbolAddress((void**)&Y, g_Y);
    cudaGetSymbolAddress((void**)&MGH, g_MGH);
    cudaGetSymbolAddress((void**)&GI, g_GI);
    cudaGetSymbolAddress((void**)&AGG, g_AGG);
    cudaGetSymbolAddress((void**)&POOL, g_POOL);
    cudaGetSymbolAddress((void**)&FC1, g_FC1);
    cudaGetSymbolAddress((void**)&BC, g_BC);
    cudaGetSymbolAddress((void**)&BIH, g_BIH);
    cudaGetSymbolAddress((void**)&BCB, g_BCB);
    cudaGetSymbolAddress((void**)&FC1T, g_FC1T);

    detect_kernel<<<1, 1>>>((const unsigned*)ei, (const unsigned*)batch, E, N);
    convert_idx<<<ceildiv(E, 256), 256>>>(ei, batch, E, N);
    for (int L = 0; L < 3; L++)
        prep_weights<<<128, 256>>>(cW[L], cwhh[L], cwih[L], cbhh[L],
                                   BC + bcOff[L], BIH + bihOff[L], BCB + bbOff[L], Cs[L]);
    transpose_fc1<<<ceildiv(128 * 256, 256), 256>>>(fc1W, FC1T);

    cudaMemcpyAsync(X, x_in, (size_t)N * 32 * sizeof(float), cudaMemcpyDeviceToDevice);

    float* xcur = X;
    float* xnext = Y;
    const int gy = ceildiv(N, 128);
    for (int L = 0; L < 3; L++) {
        const int C = Cs[L];
        const int C3 = 3 * C, C4 = 4 * C;
        for (int it = 0; it < 4; it++) {
            // [m | gh] = x @ [W(it) | whh^T]  (+ [0 | bhh])
            gemm128<<<dim3(ceildiv(C4, 128), gy), 256>>>(
                xcur, BC + bcOff[L] + (size_t)it * C * C4, BCB + bbOff[L], MGH, N, C, C4, 0);
            // agg = scatter_add(m[src] -> dst)
            cudaMemsetAsync(AGG, 0, (size_t)N * C * sizeof(float));
            long long tot = (long long)E * (C / 4);
            scatter_kernel<<<(int)((tot + 255) / 256), 256>>>(MGH, C4, AGG, E, C);
            // gi = agg @ wih^T + bih
            gemm128<<<dim3(ceildiv(C3, 128), gy), 256>>>(
                AGG, BIH + bihOff[L], cbih[L], GI, N, C, C3, 0);
            // x = GRU(gi, gh, x)
            long long tn = (long long)N * (C / 4);
            gru_kernel<<<(int)((tn + 255) / 256), 256>>>(xcur, GI, MGH, N, C);
        }
        const int Cout = (L < 2) ? Cs[L + 1] : Cs[L];
        const float* ga = (L < 2) ? bng[L] : nullptr;
        const float* be = (L < 2) ? bnb[L] : nullptr;
        const float* mn = (L < 2) ? bnm[L] : nullptr;
        const float* vr = (L < 2) ? bnv[L] : nullptr;
        long long tt = (long long)N * Cout;
        transition_kernel<<<(int)((tt + 255) / 256), 256>>>(xcur, xnext, N, C, Cout, ga, be, mn, vr);
        float* t = xcur; xcur = xnext; xnext = t;
    }

    cudaMemsetAsync(POOL, 0, 256 * 128 * sizeof(float));
    pool_kernel<<<ceildiv(N * 128, 256), 256>>>(xcur, POOL, N);

    // fc1 + ELU: [256,128] @ [128,256] -> [256,256]
    gemm128<<<dim3(2, 2), 256>>>(POOL, FC1T, fc1b, FC1, 256, 128, 256, 1);

    fc2_kernel<<<256, 32>>>(FC1, fc2W, fc2b, (float*)d_out);
}